// round 4
// baseline (speedup 1.0000x reference)
#include <cuda_runtime.h>
#include <cstdint>
#include <cstddef>

#define DI __device__ __forceinline__

// ---------------- problem constants ----------------
namespace {
constexpr int BN    = 128;
constexpr int CINc  = 64;
constexpr int NFc   = 16;
constexpr int COUTc = 256;
constexpr int Hc    = 20;
constexpr int Wc    = 20;
constexpr int HWc   = Hc * Wc;          // 400
constexpr int Kc    = CINc * NFc;       // 1024
constexpr int PP    = 21;               // padded spatial extent (index 20 == zero slot)
constexpr int PLANE = PP * PP * BN;     // floats per cin plane (56448)

constexpr int Mc      = HWc * BN;       // 51200 GEMM rows, row = hw*128 + b
constexpr int KCHUNK  = 32;
constexpr int NCHUNKS = Kc / KCHUNK;    // 32
constexpr int STAGES  = 3;

// stage = A(4096 words) + B(4096 words)
constexpr int STAGE_WORDS = 8192;
constexpr int SMEM_BYTES  = STAGES * STAGE_WORDS * 4;   // 96 KB

struct Tap { int4 off; float4 w; };
}

// ---------------- device scratch (no allocations allowed) ----------------
__device__ float    d_xt[(size_t)CINc * PLANE];          // 14.5 MB
__device__ float    d_g[(size_t)BN * HWc * COUTc];       // 52.4 MB, [b][hw][o]
__device__ Tap      d_taps[HWc * NFc];                   // 200 KB
__device__ uint32_t d_comb_p[COUTc * Kc];                // 1 MB, frag-layout tf32
__device__ uint32_t d_feat[(size_t)Mc * Kc];             // 210 MB, frag-layout tf32
// frag layout (both A and B):  [group of 16 rows][kc(32)][ks(4)] -> 512B block
//   block word = lq*16 + lc*4 + {0: (row lq,   k lc), 1: (row lq,   k lc+4),
//                                2: (row lq+8, k lc), 3: (row lq+8, k lc+4)}

// ---------------- small asm helpers ----------------
DI uint32_t smem_u32(const void* p) {
    uint32_t a;
    asm("{ .reg .u64 t; cvta.to.shared.u64 t, %1; cvt.u32.u64 %0, t; }"
        : "=r"(a) : "l"(p));
    return a;
}

DI uint32_t f2tf32(float f) {
    uint32_t u;
    asm("cvt.rna.tf32.f32 %0, %1;" : "=r"(u) : "f"(f));
    return u;
}

DI void cp_async16(uint32_t saddr, const void* gptr) {
    asm volatile("cp.async.cg.shared.global [%0], [%1], 16;"
                 :: "r"(saddr), "l"(gptr));
}
DI void cp_commit() { asm volatile("cp.async.commit_group;" ::: "memory"); }
template <int N>
DI void cp_wait() { asm volatile("cp.async.wait_group %0;" :: "n"(N) : "memory"); }

// m16n8k8 tf32 MMA, fp32 accumulate
DI void mma_tf32(float d[4], const uint32_t a[4], uint32_t b0, uint32_t b1) {
    asm volatile(
        "mma.sync.aligned.m16n8k8.row.col.f32.tf32.tf32.f32 "
        "{%0,%1,%2,%3}, {%4,%5,%6,%7}, {%8,%9}, {%0,%1,%2,%3};"
        : "+f"(d[0]), "+f"(d[1]), "+f"(d[2]), "+f"(d[3])
        : "r"(a[0]), "r"(a[1]), "r"(a[2]), "r"(a[3]), "r"(b0), "r"(b1));
}

// ---------------- kernel 1: x (B,CIN,H,W) -> xt[cin][21][21][b] ----------------
__global__ void __launch_bounds__(256) xt_kernel(const float* __restrict__ x) {
    __shared__ float tile[BN * PP];
    const int cin = blockIdx.x;
    const int i   = blockIdx.y;       // 0..20
    const int tid = threadIdx.x;
    float* dst = d_xt + (size_t)cin * PLANE + (size_t)i * PP * BN;

    if (i == Hc) {
        for (int p = tid; p < PP * BN; p += 256) dst[p] = 0.0f;
        return;
    }
    for (int p = tid; p < BN * Wc; p += 256) {
        int b = p / Wc, j = p % Wc;
        tile[b * PP + j] = x[(((size_t)b * CINc + cin) * Hc + i) * Wc + j];
    }
    __syncthreads();
    for (int p = tid; p < PP * BN; p += 256) {
        int j = p / BN, b = p % BN;
        dst[(size_t)j * BN + b] = (j < Wc) ? tile[b * PP + j] : 0.0f;
    }
}

// ---------------- kernel 2: tap table -----------------------------------------
__global__ void __launch_bounds__(256) taps_kernel(const float* __restrict__ flow) {
    int id = blockIdx.x * 256 + threadIdx.x;
    if (id >= HWc * NFc) return;
    int hw = id / NFc, nf = id % NFc;
    int h = hw / Wc, w = hw % Wc;

    float f0 = flow[(((size_t)nf * Hc + h) * Wc + w) * 2 + 0];
    float f1 = flow[(((size_t)nf * Hc + h) * Wc + w) * 2 + 1];
    float ix = (float)h + f0;
    float iy = (float)w + f1;
    float bx = floorf(ix), by = floorf(iy);
    float s = ix - bx, t = iy - by;
    int ibx = (int)bx, iby = (int)by;

    int px0 = min(max(ibx,     0), Hc);
    int px1 = min(max(ibx + 1, 0), Hc);
    int py0 = min(max(iby,     0), Wc);
    int py1 = min(max(iby + 1, 0), Wc);

    Tap tp;
    tp.off = make_int4((px0 * PP + py0) * BN,
                       (px1 * PP + py0) * BN,
                       (px0 * PP + py1) * BN,
                       (px1 * PP + py1) * BN);
    float w01 = s * (1.0f - t);   // NOTE: also used for the (bx, by+1) tap (source bug)
    tp.w = make_float4((1.0f - s) * (1.0f - t), w01, w01, s * t);
    d_taps[hw * NFc + nf] = tp;
}

// ---------------- kernel 3: comb -> tf32 in frag layout ------------------------
__global__ void __launch_bounds__(256) combp_kernel(const float* __restrict__ comb) {
    int idx = blockIdx.x * 256 + threadIdx.x;       // word index
    if (idx >= COUTc * Kc) return;
    int gn = idx >> 14;          // 16 o-groups (16384 words each)
    int r  = idx & 16383;
    int kc = r >> 9;             // 32
    int r2 = r & 511;
    int ks = r2 >> 7;            // 4
    int r3 = r2 & 127;
    int lq = r3 >> 4;
    int r4 = r3 & 15;
    int lc = r4 >> 2;
    int w  = r4 & 3;
    int o  = gn * 16 + lq + ((w >= 2) ? 8 : 0);
    int k  = kc * KCHUNK + ks * 8 + lc + ((w & 1) ? 4 : 0);
    d_comb_p[idx] = f2tf32(comb[(size_t)o * Kc + k]);
}

// ---------------- kernel 4: gather -> d_feat (frag layout, tf32) ---------------
// One CTA per pixel. thread: b = tid&127, octet-quarter og = tid>>7.
__global__ void __launch_bounds__(512) feat_kernel() {
    __shared__ Tap taps_sm[NFc];
    const int hw  = blockIdx.x;
    const int tid = threadIdx.x;
    if (tid < NFc) taps_sm[tid] = d_taps[hw * NFc + tid];
    __syncthreads();

    const int b    = tid & 127;
    const int og   = tid >> 7;                 // 0..3
    const int g    = hw * 8 + (b >> 4);        // 16-row group (row = hw*128 + b)
    const int r16  = b & 15;
    const int lq   = r16 & 7;
    const int half = r16 >> 3;

    #pragma unroll 4
    for (int it = 0; it < 32; ++it) {
        const int oct = og * 32 + it;          // k-octet 0..127
        const int cin = oct >> 1;
        const int nfb = (oct & 1) * 8;
        const float* __restrict__ plane = d_xt + (size_t)cin * PLANE + b;

        float v[8];
        #pragma unroll
        for (int j = 0; j < 8; ++j) {
            Tap tp = taps_sm[nfb + j];
            v[j] = plane[tp.off.x] * tp.w.x + plane[tp.off.y] * tp.w.y
                 + plane[tp.off.z] * tp.w.z + plane[tp.off.w] * tp.w.w;
        }
        const int kc = oct >> 2, ks = oct & 3;
        uint32_t* dst = d_feat + ((size_t)(g * NCHUNKS + kc) * 4 + ks) * 128
                        + lq * 16 + half * 2;
        #pragma unroll
        for (int lc = 0; lc < 4; ++lc) {
            uint2 pk = make_uint2(f2tf32(v[lc]), f2tf32(v[lc + 4]));
            *reinterpret_cast<uint2*>(dst + lc * 4) = pk;
        }
    }
}

// ---------------- kernel 5: pure tf32 GEMM, 128x128 tiles, 3-stage cp.async ----
// grid (400, 2): hw tile (128 rows = all b of one hw), N half (128 of 256).
// 8 warps: 2(M) x 4(N); warp tile 64x32.
__global__ void __launch_bounds__(256, 2) gemm_kernel() {
    extern __shared__ uint32_t smem[];
    const int hw   = blockIdx.x;
    const int nh   = blockIdx.y;
    const int tid  = threadIdx.x;
    const int lane = tid & 31;
    const int wid  = tid >> 5;
    const int wm   = wid >> 2;            // 0..1
    const int wn   = wid & 3;             // 0..3
    const int lq   = lane >> 2;
    const int lc   = lane & 3;

    const uint32_t sbase = smem_u32(smem);

    auto load_chunk = [&](int kc, int s) {
        #pragma unroll
        for (int i = 0; i < 8; ++i) {
            int u = tid + i * 256;                         // 16B unit, 0..2047
            int isB   = (u >= 1024);
            int u2    = u & 1023;
            int gi    = u2 >> 7;                           // group 0..7
            int inner = u2 & 127;                          // 16B within 2KB block
            const uint32_t* src = isB
                ? d_comb_p + ((size_t)((nh * 8 + gi) * NCHUNKS + kc) * 512) + inner * 4
                : d_feat   + ((size_t)((hw * 8 + gi) * NCHUNKS + kc) * 512) + inner * 4;
            uint32_t dst = sbase +
                (s * STAGE_WORDS + isB * 4096 + gi * 512 + inner * 4) * 4;
            cp_async16(dst, src);
        }
    };

    float acc[4][4][4];
    #pragma unroll
    for (int mi = 0; mi < 4; ++mi)
        #pragma unroll
        for (int nj = 0; nj < 4; ++nj)
            #pragma unroll
            for (int e = 0; e < 4; ++e) acc[mi][nj][e] = 0.0f;

    load_chunk(0, 0); cp_commit();
    load_chunk(1, 1); cp_commit();

    for (int c = 0; c < NCHUNKS; ++c) {
        if (c + 1 < NCHUNKS) cp_wait<1>(); else cp_wait<0>();
        __syncthreads();
        if (c + 2 < NCHUNKS) { load_chunk(c + 2, (c + 2) % STAGES); cp_commit(); }

        const uint32_t* A = smem + (c % STAGES) * STAGE_WORDS;
        const uint32_t* B = A + 4096;
        #pragma unroll
        for (int ks = 0; ks < 4; ++ks) {
            uint32_t a[4][4];
            #pragma unroll
            for (int mi = 0; mi < 4; ++mi) {
                uint4 v = *reinterpret_cast<const uint4*>(
                    A + ((wm * 4 + mi) * 4 + ks) * 128 + lq * 16 + lc * 4);
                a[mi][0] = v.x; a[mi][1] = v.z; a[mi][2] = v.y; a[mi][3] = v.w;
            }
            #pragma unroll
            for (int pr = 0; pr < 2; ++pr) {
                uint4 bv = *reinterpret_cast<const uint4*>(
                    B + ((wn * 2 + pr) * 4 + ks) * 128 + lq * 16 + lc * 4);
                #pragma unroll
                for (int mi = 0; mi < 4; ++mi) {
                    mma_tf32(acc[mi][pr * 2 + 0], a[mi], bv.x, bv.y);
                    mma_tf32(acc[mi][pr * 2 + 1], a[mi], bv.z, bv.w);
                }
            }
        }
        __syncthreads();
    }

    // writeback to d_g[b][hw][o] (o-contiguous float2 per thread)
    #pragma unroll
    for (int mi = 0; mi < 4; ++mi) {
        const int r0 = wm * 64 + mi * 16 + lq;            // b
        #pragma unroll
        for (int pr = 0; pr < 2; ++pr) {
            #pragma unroll
            for (int eo = 0; eo < 2; ++eo) {
                const int nj = pr * 2 + eo;
                const int o  = nh * 128 + wn * 32 + pr * 16 + eo * 8 + 2 * lc;
                *reinterpret_cast<float2*>(&d_g[((size_t)r0 * HWc + hw) * COUTc + o]) =
                    make_float2(acc[mi][nj][0], acc[mi][nj][1]);
                *reinterpret_cast<float2*>(&d_g[((size_t)(r0 + 8) * HWc + hw) * COUTc + o]) =
                    make_float2(acc[mi][nj][2], acc[mi][nj][3]);
            }
        }
    }
}

// ---------------- kernel 6: g[b][hw][o] -> out[b][o][hw] + bias ----------------
__global__ void __launch_bounds__(256) trans_kernel(const float* __restrict__ bias,
                                                    float* __restrict__ out) {
    __shared__ float tile[32][33];
    const int tx = threadIdx.x;
    const int ty = threadIdx.y;
    const int ht = blockIdx.x;         // 13
    const int ot = blockIdx.y;         // 8
    const int b  = blockIdx.z;         // 128

    #pragma unroll
    for (int k = 0; k < 4; ++k) {
        int hw = ht * 32 + ty + k * 8;
        int o  = ot * 32 + tx;
        if (hw < HWc)
            tile[ty + k * 8][tx] = d_g[((size_t)b * HWc + hw) * COUTc + o];
    }
    __syncthreads();
    #pragma unroll
    for (int k = 0; k < 4; ++k) {
        int o  = ot * 32 + ty + k * 8;
        int hw = ht * 32 + tx;
        if (hw < HWc)
            out[((size_t)b * COUTc + o) * HWc + hw] = tile[tx][ty + k * 8] + bias[o];
    }
}

// ---------------- launch ----------------
extern "C" void kernel_launch(void* const* d_in, const int* in_sizes, int n_in,
                              void* d_out, int out_size) {
    const float* x    = (const float*)d_in[0];   // (128, 64, 20, 20)
    const float* flow = (const float*)d_in[1];   // (16, 20, 20, 2)
    const float* comb = (const float*)d_in[2];   // (256, 1024)
    const float* bias = (const float*)d_in[3];   // (256,)
    float* out = (float*)d_out;                  // (128, 256, 20, 20)

    cudaFuncSetAttribute(gemm_kernel,
                         cudaFuncAttributeMaxDynamicSharedMemorySize, SMEM_BYTES);

    xt_kernel<<<dim3(CINc, PP), 256>>>(x);
    taps_kernel<<<(HWc * NFc + 255) / 256, 256>>>(flow);
    combp_kernel<<<(COUTc * Kc + 255) / 256, 256>>>(comb);
    feat_kernel<<<HWc, 512>>>();
    gemm_kernel<<<dim3(HWc, 2), 256, SMEM_BYTES>>>();
    trans_kernel<<<dim3(13, 8, BN), dim3(32, 8)>>>(bias, out);
}

// round 5
// speedup vs baseline: 2.8843x; 2.8843x over previous
#include <cuda_runtime.h>
#include <cstdint>
#include <cstddef>

#define DI __device__ __forceinline__

// ---------------- problem constants ----------------
namespace {
constexpr int BN    = 128;
constexpr int CINc  = 64;
constexpr int NFc   = 16;
constexpr int COUTc = 256;
constexpr int Hc    = 20;
constexpr int Wc    = 20;
constexpr int HWc   = Hc * Wc;          // 400
constexpr int Kc    = CINc * NFc;       // 1024
constexpr int PP    = 21;               // padded spatial extent (index 20 == zero slot)
constexpr int PLANE = PP * PP * BN;     // floats per cin plane (56448)

constexpr int Mc      = HWc * BN;       // 51200 GEMM rows, row = hw*128 + b
constexpr int KCHUNK  = 32;
constexpr int NCHUNKS = Kc / KCHUNK;    // 32
constexpr int STAGES  = 3;

// gemm stage = A(4096 words) + B(4096 words)
constexpr int STAGE_WORDS = 8192;
constexpr int SMEM_BYTES  = STAGES * STAGE_WORDS * 4;   // 96 KB

constexpr int RS = 136;                 // feat staging row stride (words)

struct Tap { int4 off; float4 w; };
}

// ---------------- device scratch (no allocations allowed) ----------------
__device__ float    d_xt[(size_t)CINc * PLANE];          // 14.5 MB
__device__ float    d_g[(size_t)BN * HWc * COUTc];       // 52.4 MB, [b][hw][o]
__device__ Tap      d_taps[HWc * NFc];                   // 200 KB
__device__ uint32_t d_comb_p[COUTc * Kc];                // 1 MB, frag-layout tf32
__device__ uint32_t d_feat[(size_t)Mc * Kc];             // 210 MB, frag-layout tf32
// frag layout (both A and B):  [group of 16 rows][kc(32)][ks(4)] -> 512B block
//   block word = lq*16 + lc*4 + {0:(row lq,  k lc), 1:(row lq,  k lc+4),
//                                2:(row lq+8,k lc), 3:(row lq+8,k lc+4)}

// ---------------- small asm helpers ----------------
DI uint32_t smem_u32(const void* p) {
    uint32_t a;
    asm("{ .reg .u64 t; cvta.to.shared.u64 t, %1; cvt.u32.u64 %0, t; }"
        : "=r"(a) : "l"(p));
    return a;
}

DI uint32_t f2tf32(float f) {
    uint32_t u;
    asm("cvt.rna.tf32.f32 %0, %1;" : "=r"(u) : "f"(f));
    return u;
}

DI void cp_async16(uint32_t saddr, const void* gptr) {
    asm volatile("cp.async.cg.shared.global [%0], [%1], 16;"
                 :: "r"(saddr), "l"(gptr));
}
DI void cp_commit() { asm volatile("cp.async.commit_group;" ::: "memory"); }
template <int N>
DI void cp_wait() { asm volatile("cp.async.wait_group %0;" :: "n"(N) : "memory"); }

// m16n8k8 tf32 MMA, fp32 accumulate
DI void mma_tf32(float d[4], const uint32_t a[4], uint32_t b0, uint32_t b1) {
    asm volatile(
        "mma.sync.aligned.m16n8k8.row.col.f32.tf32.tf32.f32 "
        "{%0,%1,%2,%3}, {%4,%5,%6,%7}, {%8,%9}, {%0,%1,%2,%3};"
        : "+f"(d[0]), "+f"(d[1]), "+f"(d[2]), "+f"(d[3])
        : "r"(a[0]), "r"(a[1]), "r"(a[2]), "r"(a[3]), "r"(b0), "r"(b1));
}

// ---------------- kernel 1: x (B,CIN,H,W) -> xt[cin][21][21][b] ----------------
__global__ void __launch_bounds__(256) xt_kernel(const float* __restrict__ x) {
    __shared__ float tile[BN * PP];
    const int cin = blockIdx.x;
    const int i   = blockIdx.y;       // 0..20
    const int tid = threadIdx.x;
    float* dst = d_xt + (size_t)cin * PLANE + (size_t)i * PP * BN;

    if (i == Hc) {
        for (int p = tid; p < PP * BN; p += 256) dst[p] = 0.0f;
        return;
    }
    for (int p = tid; p < BN * Wc; p += 256) {
        int b = p / Wc, j = p % Wc;
        tile[b * PP + j] = x[(((size_t)b * CINc + cin) * Hc + i) * Wc + j];
    }
    __syncthreads();
    for (int p = tid; p < PP * BN; p += 256) {
        int j = p / BN, b = p % BN;
        dst[(size_t)j * BN + b] = (j < Wc) ? tile[b * PP + j] : 0.0f;
    }
}

// ---------------- kernel 2: tap table -----------------------------------------
__global__ void __launch_bounds__(256) taps_kernel(const float* __restrict__ flow) {
    int id = blockIdx.x * 256 + threadIdx.x;
    if (id >= HWc * NFc) return;
    int hw = id / NFc, nf = id % NFc;
    int h = hw / Wc, w = hw % Wc;

    float f0 = flow[(((size_t)nf * Hc + h) * Wc + w) * 2 + 0];
    float f1 = flow[(((size_t)nf * Hc + h) * Wc + w) * 2 + 1];
    float ix = (float)h + f0;
    float iy = (float)w + f1;
    float bx = floorf(ix), by = floorf(iy);
    float s = ix - bx, t = iy - by;
    int ibx = (int)bx, iby = (int)by;

    int px0 = min(max(ibx,     0), Hc);
    int px1 = min(max(ibx + 1, 0), Hc);
    int py0 = min(max(iby,     0), Wc);
    int py1 = min(max(iby + 1, 0), Wc);

    Tap tp;
    tp.off = make_int4((px0 * PP + py0) * BN,
                       (px1 * PP + py0) * BN,
                       (px0 * PP + py1) * BN,
                       (px1 * PP + py1) * BN);
    float w01 = s * (1.0f - t);   // NOTE: also used for the (bx, by+1) tap (source bug)
    tp.w = make_float4((1.0f - s) * (1.0f - t), w01, w01, s * t);
    d_taps[hw * NFc + nf] = tp;
}

// ---------------- kernel 3: comb -> tf32 in frag layout ------------------------
__global__ void __launch_bounds__(256) combp_kernel(const float* __restrict__ comb) {
    int idx = blockIdx.x * 256 + threadIdx.x;       // word index
    if (idx >= COUTc * Kc) return;
    int gn = idx >> 14;          // 16 o-groups (16384 words each)
    int r  = idx & 16383;
    int kc = r >> 9;             // 32
    int r2 = r & 511;
    int ks = r2 >> 7;            // 4
    int r3 = r2 & 127;
    int lq = r3 >> 4;
    int r4 = r3 & 15;
    int lc = r4 >> 2;
    int w  = r4 & 3;
    int o  = gn * 16 + lq + ((w >= 2) ? 8 : 0);
    int k  = kc * KCHUNK + ks * 8 + lc + ((w & 1) ? 4 : 0);
    d_comb_p[idx] = f2tf32(comb[(size_t)o * Kc + k]);
}

// ---------------- kernel 4: gather -> d_feat (two-pass smem staging) -----------
// grid (400 hw, 4 kc-slices), 256 threads.
// Pass 1: coalesced float4-over-b gathers into sbuf[k][b] (row stride 136).
// Pass 2: conflict-free frag-order LDS + one coalesced STG.128 per thread.
__global__ void __launch_bounds__(256) feat_kernel() {
    __shared__ float sbuf[KCHUNK * RS];    // 17408 B
    __shared__ Tap taps_sm[NFc];
    const int hw  = blockIdx.x;
    const int tid = threadIdx.x;
    if (tid < NFc) taps_sm[tid] = d_taps[hw * NFc + tid];
    __syncthreads();

    const int kq = tid >> 5;               // pass1: warp -> 4 k rows
    const int b0 = (tid & 31) * 4;         // pass1: 4 consecutive b
    const int gi = tid >> 5;               // pass2: 16-row group 0..7
    const int lq = (tid & 31) >> 2;        // pass2
    const int lc = tid & 3;                // pass2

    const int kc_beg = blockIdx.y * (NCHUNKS / 4);
    for (int kc = kc_beg; kc < kc_beg + NCHUNKS / 4; ++kc) {
        // ---- pass 1: gather ----
        #pragma unroll
        for (int j = 0; j < 4; ++j) {
            const int kl  = kq * 4 + j;
            const int cin = kc * 2 + (kl >> 4);
            const Tap tp  = taps_sm[kl & 15];
            const float* __restrict__ plane = d_xt + (size_t)cin * PLANE;
            float4 v0 = *reinterpret_cast<const float4*>(plane + tp.off.x + b0);
            float4 v1 = *reinterpret_cast<const float4*>(plane + tp.off.y + b0);
            float4 v2 = *reinterpret_cast<const float4*>(plane + tp.off.z + b0);
            float4 v3 = *reinterpret_cast<const float4*>(plane + tp.off.w + b0);
            float4 r;
            r.x = v0.x * tp.w.x + v1.x * tp.w.y + v2.x * tp.w.z + v3.x * tp.w.w;
            r.y = v0.y * tp.w.x + v1.y * tp.w.y + v2.y * tp.w.z + v3.y * tp.w.w;
            r.z = v0.z * tp.w.x + v1.z * tp.w.y + v2.z * tp.w.z + v3.z * tp.w.w;
            r.w = v0.w * tp.w.x + v1.w * tp.w.y + v2.w * tp.w.z + v3.w * tp.w.w;
            *reinterpret_cast<float4*>(&sbuf[kl * RS + b0]) = r;
        }
        __syncthreads();
        // ---- pass 2: frag-order convert + coalesced store ----
        uint32_t* dstb = d_feat + ((size_t)((hw * 8 + gi) * NCHUNKS + kc)) * 512
                         + lq * 16 + lc * 4;
        #pragma unroll
        for (int ks = 0; ks < 4; ++ks) {
            const int kr = ks * 8 + lc;
            const int br = gi * 16 + lq;
            uint4 pk;
            pk.x = f2tf32(sbuf[kr * RS + br]);
            pk.y = f2tf32(sbuf[(kr + 4) * RS + br]);
            pk.z = f2tf32(sbuf[kr * RS + br + 8]);
            pk.w = f2tf32(sbuf[(kr + 4) * RS + br + 8]);
            *reinterpret_cast<uint4*>(dstb + ks * 128) = pk;
        }
        __syncthreads();
    }
}

// ---------------- kernel 5: pure tf32 GEMM, 128x128 tiles, 3-stage cp.async ----
// grid (400, 2): hw tile (128 rows = all b of one hw), N half (128 of 256).
// 8 warps: 2(M) x 4(N); warp tile 64x32.
__global__ void __launch_bounds__(256, 2) gemm_kernel() {
    extern __shared__ uint32_t smem[];
    const int hw   = blockIdx.x;
    const int nh   = blockIdx.y;
    const int tid  = threadIdx.x;
    const int lane = tid & 31;
    const int wid  = tid >> 5;
    const int wm   = wid >> 2;            // 0..1
    const int wn   = wid & 3;             // 0..3
    const int lq   = lane >> 2;
    const int lc   = lane & 3;

    const uint32_t sbase = smem_u32(smem);

    auto load_chunk = [&](int kc, int s) {
        #pragma unroll
        for (int i = 0; i < 8; ++i) {
            int u = tid + i * 256;                         // 16B unit, 0..2047
            int isB   = (u >= 1024);
            int u2    = u & 1023;
            int gi    = u2 >> 7;                           // group 0..7
            int inner = u2 & 127;                          // 16B within 2KB block
            const uint32_t* src = isB
                ? d_comb_p + ((size_t)((nh * 8 + gi) * NCHUNKS + kc) * 512) + inner * 4
                : d_feat   + ((size_t)((hw * 8 + gi) * NCHUNKS + kc) * 512) + inner * 4;
            uint32_t dst = sbase +
                (s * STAGE_WORDS + isB * 4096 + gi * 512 + inner * 4) * 4;
            cp_async16(dst, src);
        }
    };

    float acc[4][4][4];
    #pragma unroll
    for (int mi = 0; mi < 4; ++mi)
        #pragma unroll
        for (int nj = 0; nj < 4; ++nj)
            #pragma unroll
            for (int e = 0; e < 4; ++e) acc[mi][nj][e] = 0.0f;

    load_chunk(0, 0); cp_commit();
    load_chunk(1, 1); cp_commit();

    for (int c = 0; c < NCHUNKS; ++c) {
        if (c + 1 < NCHUNKS) cp_wait<1>(); else cp_wait<0>();
        __syncthreads();
        if (c + 2 < NCHUNKS) { load_chunk(c + 2, (c + 2) % STAGES); cp_commit(); }

        const uint32_t* A = smem + (c % STAGES) * STAGE_WORDS;
        const uint32_t* B = A + 4096;
        #pragma unroll
        for (int ks = 0; ks < 4; ++ks) {
            uint32_t a[4][4];
            #pragma unroll
            for (int mi = 0; mi < 4; ++mi) {
                uint4 v = *reinterpret_cast<const uint4*>(
                    A + ((wm * 4 + mi) * 4 + ks) * 128 + lq * 16 + lc * 4);
                a[mi][0] = v.x; a[mi][1] = v.z; a[mi][2] = v.y; a[mi][3] = v.w;
            }
            #pragma unroll
            for (int pr = 0; pr < 2; ++pr) {
                uint4 bv = *reinterpret_cast<const uint4*>(
                    B + ((wn * 2 + pr) * 4 + ks) * 128 + lq * 16 + lc * 4);
                #pragma unroll
                for (int mi = 0; mi < 4; ++mi) {
                    mma_tf32(acc[mi][pr * 2 + 0], a[mi], bv.x, bv.y);
                    mma_tf32(acc[mi][pr * 2 + 1], a[mi], bv.z, bv.w);
                }
            }
        }
        __syncthreads();
    }

    // writeback to d_g[b][hw][o]
    #pragma unroll
    for (int mi = 0; mi < 4; ++mi) {
        const int r0 = wm * 64 + mi * 16 + lq;            // b
        #pragma unroll
        for (int pr = 0; pr < 2; ++pr) {
            #pragma unroll
            for (int eo = 0; eo < 2; ++eo) {
                const int nj = pr * 2 + eo;
                const int o  = nh * 128 + wn * 32 + pr * 16 + eo * 8 + 2 * lc;
                *reinterpret_cast<float2*>(&d_g[((size_t)r0 * HWc + hw) * COUTc + o]) =
                    make_float2(acc[mi][nj][0], acc[mi][nj][1]);
                *reinterpret_cast<float2*>(&d_g[((size_t)(r0 + 8) * HWc + hw) * COUTc + o]) =
                    make_float2(acc[mi][nj][2], acc[mi][nj][3]);
            }
        }
    }
}

// ---------------- kernel 6: g[b][hw][o] -> out[b][o][hw] + bias ----------------
__global__ void __launch_bounds__(256) trans_kernel(const float* __restrict__ bias,
                                                    float* __restrict__ out) {
    __shared__ float tile[32][33];
    const int tx = threadIdx.x;
    const int ty = threadIdx.y;
    const int ht = blockIdx.x;         // 13
    const int ot = blockIdx.y;         // 8
    const int b  = blockIdx.z;         // 128

    #pragma unroll
    for (int k = 0; k < 4; ++k) {
        int hw = ht * 32 + ty + k * 8;
        int o  = ot * 32 + tx;
        if (hw < HWc)
            tile[ty + k * 8][tx] = d_g[((size_t)b * HWc + hw) * COUTc + o];
    }
    __syncthreads();
    #pragma unroll
    for (int k = 0; k < 4; ++k) {
        int o  = ot * 32 + ty + k * 8;
        int hw = ht * 32 + tx;
        if (hw < HWc)
            out[((size_t)b * COUTc + o) * HWc + hw] = tile[tx][ty + k * 8] + bias[o];
    }
}

// ---------------- launch ----------------
extern "C" void kernel_launch(void* const* d_in, const int* in_sizes, int n_in,
                              void* d_out, int out_size) {
    const float* x    = (const float*)d_in[0];   // (128, 64, 20, 20)
    const float* flow = (const float*)d_in[1];   // (16, 20, 20, 2)
    const float* comb = (const float*)d_in[2];   // (256, 1024)
    const float* bias = (const float*)d_in[3];   // (256,)
    float* out = (float*)d_out;                  // (128, 256, 20, 20)

    cudaFuncSetAttribute(gemm_kernel,
                         cudaFuncAttributeMaxDynamicSharedMemorySize, SMEM_BYTES);

    xt_kernel<<<dim3(CINc, PP), 256>>>(x);
    taps_kernel<<<(HWc * NFc + 255) / 256, 256>>>(flow);
    combp_kernel<<<(COUTc * Kc + 255) / 256, 256>>>(comb);
    feat_kernel<<<dim3(HWc, 4), 256>>>();
    gemm_kernel<<<dim3(HWc, 2), 256, SMEM_BYTES>>>();
    trans_kernel<<<dim3(13, 8, BN), dim3(32, 8)>>>(bias, out);
}

// round 7
// speedup vs baseline: 2.8907x; 1.0022x over previous
#include <cuda_runtime.h>
#include <cstdint>
#include <cstddef>

#define DI __device__ __forceinline__

// ---------------- problem constants ----------------
namespace {
constexpr int BN    = 128;
constexpr int CINc  = 64;
constexpr int NFc   = 16;
constexpr int COUTc = 256;
constexpr int Hc    = 20;
constexpr int Wc    = 20;
constexpr int HWc   = Hc * Wc;          // 400
constexpr int Kc    = CINc * NFc;       // 1024
constexpr int PP    = 21;               // padded spatial extent (index 20 == zero slot)
constexpr int PLANE = PP * PP * BN;     // floats per cin plane (56448)

constexpr int Mc      = HWc * BN;       // 51200 GEMM rows, row = hw*128 + b
constexpr int KCHUNK  = 32;
constexpr int NCHUNKS = Kc / KCHUNK;    // 32
constexpr int STAGES  = 3;

// gemm stage = A(4096 words) + B(4096 words)
constexpr int STAGE_WORDS = 8192;
constexpr int SMEM_BYTES  = STAGES * STAGE_WORDS * 4;   // 96 KB

constexpr int RS = 136;                 // feat staging row stride (words)

struct Tap { int4 off; float4 w; };
}

// ---------------- device scratch (no allocations allowed) ----------------
__device__ float    d_xt[(size_t)CINc * PLANE];          // 14.5 MB
__device__ float    d_g[(size_t)BN * HWc * COUTc];       // 52.4 MB, [b][hw][o]
__device__ Tap      d_taps[HWc * NFc];                   // 200 KB
__device__ uint32_t d_comb_p[COUTc * Kc];                // 1 MB, frag-layout tf32
__device__ uint32_t d_feat[(size_t)Mc * Kc];             // 210 MB, frag-layout tf32
// frag layout (both A and B):  [group of 16 rows][kc(32)][ks(4)] -> 512B block
//   block word = lq*16 + lc*4 + {0:(row lq,  k lc), 1:(row lq,  k lc+4),
//                                2:(row lq+8,k lc), 3:(row lq+8,k lc+4)}

// ---------------- small asm helpers ----------------
DI uint32_t smem_u32(const void* p) {
    uint32_t a;
    asm("{ .reg .u64 t; cvta.to.shared.u64 t, %1; cvt.u32.u64 %0, t; }"
        : "=r"(a) : "l"(p));
    return a;
}

DI uint32_t f2tf32(float f) {
    uint32_t u;
    asm("cvt.rna.tf32.f32 %0, %1;" : "=r"(u) : "f"(f));
    return u;
}

DI void cp_async16(uint32_t saddr, const void* gptr) {
    asm volatile("cp.async.cg.shared.global [%0], [%1], 16;"
                 :: "r"(saddr), "l"(gptr));
}
DI void cp_commit() { asm volatile("cp.async.commit_group;" ::: "memory"); }
template <int N>
DI void cp_wait() { asm volatile("cp.async.wait_group %0;" :: "n"(N) : "memory"); }

// m16n8k8 tf32 MMA, fp32 accumulate
DI void mma_tf32(float d[4], const uint32_t a[4], uint32_t b0, uint32_t b1) {
    asm volatile(
        "mma.sync.aligned.m16n8k8.row.col.f32.tf32.tf32.f32 "
        "{%0,%1,%2,%3}, {%4,%5,%6,%7}, {%8,%9}, {%0,%1,%2,%3};"
        : "+f"(d[0]), "+f"(d[1]), "+f"(d[2]), "+f"(d[3])
        : "r"(a[0]), "r"(a[1]), "r"(a[2]), "r"(a[3]), "r"(b0), "r"(b1));
}

// ---------------- kernel 1: x (B,CIN,H,W) -> xt[cin][21][21][b] ----------------
__global__ void __launch_bounds__(256) xt_kernel(const float* __restrict__ x) {
    __shared__ float tile[BN * PP];
    const int cin = blockIdx.x;
    const int i   = blockIdx.y;       // 0..20
    const int tid = threadIdx.x;
    float* dst = d_xt + (size_t)cin * PLANE + (size_t)i * PP * BN;

    if (i == Hc) {
        for (int p = tid; p < PP * BN; p += 256) dst[p] = 0.0f;
        return;
    }
    for (int p = tid; p < BN * Wc; p += 256) {
        int b = p / Wc, j = p % Wc;
        tile[b * PP + j] = x[(((size_t)b * CINc + cin) * Hc + i) * Wc + j];
    }
    __syncthreads();
    for (int p = tid; p < PP * BN; p += 256) {
        int j = p / BN, b = p % BN;
        dst[(size_t)j * BN + b] = (j < Wc) ? tile[b * PP + j] : 0.0f;
    }
}

// ---------------- kernel 2: tap table -----------------------------------------
__global__ void __launch_bounds__(256) taps_kernel(const float* __restrict__ flow) {
    int id = blockIdx.x * 256 + threadIdx.x;
    if (id >= HWc * NFc) return;
    int hw = id / NFc, nf = id % NFc;
    int h = hw / Wc, w = hw % Wc;

    float f0 = flow[(((size_t)nf * Hc + h) * Wc + w) * 2 + 0];
    float f1 = flow[(((size_t)nf * Hc + h) * Wc + w) * 2 + 1];
    float ix = (float)h + f0;
    float iy = (float)w + f1;
    float bx = floorf(ix), by = floorf(iy);
    float s = ix - bx, t = iy - by;
    int ibx = (int)bx, iby = (int)by;

    int px0 = min(max(ibx,     0), Hc);
    int px1 = min(max(ibx + 1, 0), Hc);
    int py0 = min(max(iby,     0), Wc);
    int py1 = min(max(iby + 1, 0), Wc);

    Tap tp;
    tp.off = make_int4((px0 * PP + py0) * BN,
                       (px1 * PP + py0) * BN,
                       (px0 * PP + py1) * BN,
                       (px1 * PP + py1) * BN);
    float w01 = s * (1.0f - t);   // NOTE: also used for the (bx, by+1) tap (source bug)
    tp.w = make_float4((1.0f - s) * (1.0f - t), w01, w01, s * t);
    d_taps[hw * NFc + nf] = tp;
}

// ---------------- kernel 3: comb -> tf32 in frag layout ------------------------
__global__ void __launch_bounds__(256) combp_kernel(const float* __restrict__ comb) {
    int idx = blockIdx.x * 256 + threadIdx.x;       // word index
    if (idx >= COUTc * Kc) return;
    int gn = idx >> 14;          // 16 o-groups (16384 words each)
    int r  = idx & 16383;
    int kc = r >> 9;             // 32
    int r2 = r & 511;
    int ks = r2 >> 7;            // 4
    int r3 = r2 & 127;
    int lq = r3 >> 4;
    int r4 = r3 & 15;
    int lc = r4 >> 2;
    int w  = r4 & 3;
    int o  = gn * 16 + lq + ((w >= 2) ? 8 : 0);
    int k  = kc * KCHUNK + ks * 8 + lc + ((w & 1) ? 4 : 0);
    d_comb_p[idx] = f2tf32(comb[(size_t)o * Kc + k]);
}

// ---------------- kernel 4: gather -> d_feat (two-pass smem staging) -----------
// grid (400 hw, 4 kc-slices), 256 threads.
__global__ void __launch_bounds__(256) feat_kernel() {
    __shared__ float sbuf[KCHUNK * RS];    // 17408 B
    __shared__ Tap taps_sm[NFc];
    const int hw  = blockIdx.x;
    const int tid = threadIdx.x;
    if (tid < NFc) taps_sm[tid] = d_taps[hw * NFc + tid];
    __syncthreads();

    const int kq = tid >> 5;               // pass1: warp -> 4 k rows
    const int b0 = (tid & 31) * 4;         // pass1: 4 consecutive b
    const int gi = tid >> 5;               // pass2: 16-row group 0..7
    const int lq = (tid & 31) >> 2;        // pass2
    const int lc = tid & 3;                // pass2

    const int kc_beg = blockIdx.y * (NCHUNKS / 4);
    for (int kc = kc_beg; kc < kc_beg + NCHUNKS / 4; ++kc) {
        // ---- pass 1: gather ----
        #pragma unroll
        for (int j = 0; j < 4; ++j) {
            const int kl  = kq * 4 + j;
            const int cin = kc * 2 + (kl >> 4);
            const Tap tp  = taps_sm[kl & 15];
            const float* __restrict__ plane = d_xt + (size_t)cin * PLANE;
            float4 v0 = *reinterpret_cast<const float4*>(plane + tp.off.x + b0);
            float4 v1 = *reinterpret_cast<const float4*>(plane + tp.off.y + b0);
            float4 v2 = *reinterpret_cast<const float4*>(plane + tp.off.z + b0);
            float4 v3 = *reinterpret_cast<const float4*>(plane + tp.off.w + b0);
            float4 r;
            r.x = v0.x * tp.w.x + v1.x * tp.w.y + v2.x * tp.w.z + v3.x * tp.w.w;
            r.y = v0.y * tp.w.x + v1.y * tp.w.y + v2.y * tp.w.z + v3.y * tp.w.w;
            r.z = v0.z * tp.w.x + v1.z * tp.w.y + v2.z * tp.w.z + v3.z * tp.w.w;
            r.w = v0.w * tp.w.x + v1.w * tp.w.y + v2.w * tp.w.z + v3.w * tp.w.w;
            *reinterpret_cast<float4*>(&sbuf[kl * RS + b0]) = r;
        }
        __syncthreads();
        // ---- pass 2: frag-order convert + coalesced store ----
        uint32_t* dstb = d_feat + ((size_t)((hw * 8 + gi) * NCHUNKS + kc)) * 512
                         + lq * 16 + lc * 4;
        #pragma unroll
        for (int ks = 0; ks < 4; ++ks) {
            const int kr = ks * 8 + lc;
            const int br = gi * 16 + lq;
            uint4 pk;
            pk.x = f2tf32(sbuf[kr * RS + br]);
            pk.y = f2tf32(sbuf[(kr + 4) * RS + br]);
            pk.z = f2tf32(sbuf[kr * RS + br + 8]);
            pk.w = f2tf32(sbuf[(kr + 4) * RS + br + 8]);
            *reinterpret_cast<uint4*>(dstb + ks * 128) = pk;
        }
        __syncthreads();
    }
}

// ---------------- kernel 5: pure tf32 GEMM, 128x128 tiles, 3-stage cp.async ----
// grid (2, 400): nh FASTEST so both N-halves of one hw run adjacently and the
// second d_feat read hits L2 instead of DRAM.
// 8 warps: 2(M) x 4(N); warp tile 64x32.
__global__ void __launch_bounds__(256, 2) gemm_kernel() {
    extern __shared__ uint32_t smem[];
    const int nh   = blockIdx.x;          // 0..1 (fast axis)
    const int hw   = blockIdx.y;          // 0..399
    const int tid  = threadIdx.x;
    const int lane = tid & 31;
    const int wid  = tid >> 5;
    const int wm   = wid >> 2;            // 0..1
    const int wn   = wid & 3;             // 0..3
    const int lq   = lane >> 2;
    const int lc   = lane & 3;

    const uint32_t sbase = smem_u32(smem);

    auto load_chunk = [&](int kc, int s) {
        #pragma unroll
        for (int i = 0; i < 8; ++i) {
            int u = tid + i * 256;                         // 16B unit, 0..2047
            int isB   = (u >= 1024);
            int u2    = u & 1023;
            int gi    = u2 >> 7;                           // group 0..7
            int inner = u2 & 127;                          // 16B within 2KB block
            const uint32_t* src = isB
                ? d_comb_p + ((size_t)((nh * 8 + gi) * NCHUNKS + kc) * 512) + inner * 4
                : d_feat   + ((size_t)((hw * 8 + gi) * NCHUNKS + kc) * 512) + inner * 4;
            uint32_t dst = sbase +
                (s * STAGE_WORDS + isB * 4096 + gi * 512 + inner * 4) * 4;
            cp_async16(dst, src);
        }
    };

    float acc[4][4][4];
    #pragma unroll
    for (int mi = 0; mi < 4; ++mi)
        #pragma unroll
        for (int nj = 0; nj < 4; ++nj)
            #pragma unroll
            for (int e = 0; e < 4; ++e) acc[mi][nj][e] = 0.0f;

    load_chunk(0, 0); cp_commit();
    load_chunk(1, 1); cp_commit();

    for (int c = 0; c < NCHUNKS; ++c) {
        if (c + 1 < NCHUNKS) cp_wait<1>(); else cp_wait<0>();
        __syncthreads();
        if (c + 2 < NCHUNKS) { load_chunk(c + 2, (c + 2) % STAGES); cp_commit(); }

        const uint32_t* A = smem + (c % STAGES) * STAGE_WORDS;
        const uint32_t* B = A + 4096;
        #pragma unroll
        for (int ks = 0; ks < 4; ++ks) {
            uint32_t a[4][4];
            #pragma unroll
            for (int mi = 0; mi < 4; ++mi) {
                uint4 v = *reinterpret_cast<const uint4*>(
                    A + ((wm * 4 + mi) * 4 + ks) * 128 + lq * 16 + lc * 4);
                a[mi][0] = v.x; a[mi][1] = v.z; a[mi][2] = v.y; a[mi][3] = v.w;
            }
            #pragma unroll
            for (int pr = 0; pr < 2; ++pr) {
                uint4 bv = *reinterpret_cast<const uint4*>(
                    B + ((wn * 2 + pr) * 4 + ks) * 128 + lq * 16 + lc * 4);
                #pragma unroll
                for (int mi = 0; mi < 4; ++mi) {
                    mma_tf32(acc[mi][pr * 2 + 0], a[mi], bv.x, bv.y);
                    mma_tf32(acc[mi][pr * 2 + 1], a[mi], bv.z, bv.w);
                }
            }
        }
        __syncthreads();
    }

    // writeback to d_g[b][hw][o]
    #pragma unroll
    for (int mi = 0; mi < 4; ++mi) {
        const int r0 = wm * 64 + mi * 16 + lq;            // b
        #pragma unroll
        for (int pr = 0; pr < 2; ++pr) {
            #pragma unroll
            for (int eo = 0; eo < 2; ++eo) {
                const int nj = pr * 2 + eo;
                const int o  = nh * 128 + wn * 32 + pr * 16 + eo * 8 + 2 * lc;
                *reinterpret_cast<float2*>(&d_g[((size_t)r0 * HWc + hw) * COUTc + o]) =
                    make_float2(acc[mi][nj][0], acc[mi][nj][1]);
                *reinterpret_cast<float2*>(&d_g[((size_t)(r0 + 8) * HWc + hw) * COUTc + o]) =
                    make_float2(acc[mi][nj][2], acc[mi][nj][3]);
            }
        }
    }
}

// ---------------- kernel 6: g[b][hw][o] -> out[b][o][hw] + bias (float4) -------
// 32x32 tile per block, FLAT 256-thread block (tid spans 0..255), float4 on
// both global sides. 400 = 12*32 + 16: partial tiles remain whole-float4 in hw.
__global__ void __launch_bounds__(256) trans_kernel(const float* __restrict__ bias,
                                                    float* __restrict__ out) {
    __shared__ float tile[32][33];
    const int tid = threadIdx.x;       // 0..255
    const int ht  = blockIdx.x;        // 13
    const int ot  = blockIdx.y;        // 8
    const int b   = blockIdx.z;        // 128

    // load: thread -> (hw_l = tid>>3, o4 = tid&7), one float4 over o
    {
        const int hw_l = tid >> 3;
        const int o4   = tid & 7;
        const int hw   = ht * 32 + hw_l;
        if (hw < HWc) {
            float4 v = *reinterpret_cast<const float4*>(
                &d_g[((size_t)b * HWc + hw) * COUTc + ot * 32 + o4 * 4]);
            tile[hw_l][o4 * 4 + 0] = v.x;
            tile[hw_l][o4 * 4 + 1] = v.y;
            tile[hw_l][o4 * 4 + 2] = v.z;
            tile[hw_l][o4 * 4 + 3] = v.w;
        }
    }
    __syncthreads();
    // store: thread -> (o_l = tid>>3, hw4 = tid&7), one float4 over hw
    {
        const int o_l = tid >> 3;
        const int hw4 = tid & 7;
        const int hw0 = ht * 32 + hw4 * 4;
        if (hw0 < HWc) {
            const int o = ot * 32 + o_l;
            const float bv = bias[o];
            float4 v;
            v.x = tile[hw4 * 4 + 0][o_l] + bv;
            v.y = tile[hw4 * 4 + 1][o_l] + bv;
            v.z = tile[hw4 * 4 + 2][o_l] + bv;
            v.w = tile[hw4 * 4 + 3][o_l] + bv;
            *reinterpret_cast<float4*>(&out[((size_t)b * COUTc + o) * HWc + hw0]) = v;
        }
    }
}

// ---------------- launch ----------------
extern "C" void kernel_launch(void* const* d_in, const int* in_sizes, int n_in,
                              void* d_out, int out_size) {
    const float* x    = (const float*)d_in[0];   // (128, 64, 20, 20)
    const float* flow = (const float*)d_in[1];   // (16, 20, 20, 2)
    const float* comb = (const float*)d_in[2];   // (256, 1024)
    const float* bias = (const float*)d_in[3];   // (256,)
    float* out = (float*)d_out;                  // (128, 256, 20, 20)

    cudaFuncSetAttribute(gemm_kernel,
                         cudaFuncAttributeMaxDynamicSharedMemorySize, SMEM_BYTES);

    xt_kernel<<<dim3(CINc, PP), 256>>>(x);
    taps_kernel<<<(HWc * NFc + 255) / 256, 256>>>(flow);
    combp_kernel<<<(COUTc * Kc + 255) / 256, 256>>>(comb);
    feat_kernel<<<dim3(HWc, 4), 256>>>();
    gemm_kernel<<<dim3(2, HWc), 256, SMEM_BYTES>>>();
    trans_kernel<<<dim3(13, 8, BN), 256>>>(bias, out);
}